// round 15
// baseline (speedup 1.0000x reference)
#include <cuda_runtime.h>
#include <cuda_fp16.h>
#include <cstdint>

#define NN 20000
#define EE 320000
#define TE (EE + NN)          // edges + self loops
#define FIN 128
#define HID 64
#define HEADS 8
#define C1 (HEADS * HID)      // 512
#define NBLK ((NN + 255) / 256)   // 79 scan blocks
#define CB ((TE / 2 + 255) / 256) // 665 count/scatter blocks
#define XB (NN * FIN / 4 / 256)   // 2500 x-convert blocks
#define WB (FIN * C1 / 256)       // 256 w-convert blocks

// ---------------- scratch (static device globals; no allocation) -------------
__device__ int    g_is64;
__device__ int    g_cnt[NN];
__device__ int    g_off[NN + 1];
__device__ int    g_cur[NN];
__device__ int    g_csr[TE];
__device__ int    g_bsum[NBLK];
__device__ __half g_h1[(size_t)NN * C1];      // 20 MB, fp16 features
__device__ __half g_xhp[(size_t)NN * FIN];    // fp16 x            [N][128]
__device__ __half g_wth[C1 * FIN];            // fp16 W1^T         [n][k]
__device__ float  g_as1[NN * HEADS];
__device__ float  g_ad1[NN * HEADS];
__device__ float  g_h2[NN * 2];
__device__ float  g_as2[NN];
__device__ float  g_ad2[NN];

// ---------------- conversions: x->fp16 + W1^T->fp16 (main stream) ------------
__global__ void k_conv(const float* __restrict__ x, const float* __restrict__ W1) {
    int b = blockIdx.x, t = threadIdx.x;
    if (b < XB) {
        int i = b * 256 + t;
        float4 v = ((const float4*)x)[i];
        ((__half2*)g_xhp)[2 * i + 0] = __floats2half2_rn(v.x, v.y);
        ((__half2*)g_xhp)[2 * i + 1] = __floats2half2_rn(v.z, v.w);
    } else {
        int j = (b - XB) * 256 + t;
        int k = j / C1, n = j % C1;
        g_wth[n * FIN + k] = __float2half_rn(W1[j]);
    }
}

// ---------------- CSR build (side stream) -------------------------------------
__global__ void k_count(const void* __restrict__ ei) {
    __shared__ int is64_s;
    int b = blockIdx.x, t = threadIdx.x;
    if (t < 32) {
        int hi = ((const int*)ei)[2 * t + 1];
        unsigned bl = __ballot_sync(0xffffffffu, hi == 0);
        if (t == 0) {
            is64_s = (bl == 0xffffffffu) ? 1 : 0;
            if (b == 0) g_is64 = is64_s;
        }
    }
    __syncthreads();
    int p = b * 256 + t;
    if (p >= TE / 2) return;
    int d0, d1;
    if (2 * p < EE) {
        if (is64_s) {
            longlong2 v = ((const longlong2*)ei)[EE / 2 + p];
            d0 = (int)v.x; d1 = (int)v.y;
        } else {
            int2 v = ((const int2*)ei)[EE / 2 + p];
            d0 = v.x; d1 = v.y;
        }
    } else {
        d0 = 2 * p - EE; d1 = d0 + 1;
    }
    if (d0 == d1) atomicAdd(&g_cnt[d0], 2);
    else { atomicAdd(&g_cnt[d0], 1); atomicAdd(&g_cnt[d1], 1); }
}

__global__ void k_scanA() {
    int t = threadIdx.x, b = blockIdx.x;
    int i = b * 256 + t;
    int v = (i < NN) ? g_cnt[i] : 0;
    int lane = t & 31, wid = t >> 5;
    int incl = v;
    #pragma unroll
    for (int o = 1; o < 32; o <<= 1) {
        int x = __shfl_up_sync(0xffffffffu, incl, o);
        if (lane >= o) incl += x;
    }
    __shared__ int ws[8];
    if (lane == 31) ws[wid] = incl;
    __syncthreads();
    if (t < 8) {
        int wv = ws[t];
        int wincl = wv;
        #pragma unroll
        for (int o = 1; o < 8; o <<= 1) {
            int x = __shfl_up_sync(0x000000ffu, wincl, o);
            if (t >= o) wincl += x;
        }
        ws[t] = wincl - wv;
        if (t == 7) g_bsum[b] = wincl;
    }
    __syncthreads();
    incl += ws[wid];
    if (i < NN) g_off[i + 1] = incl;
}

__global__ void k_scanC() {
    __shared__ int carry_s;
    int t = threadIdx.x, b = blockIdx.x;
    if (t < 32) {
        int c = 0;
        for (int i = t; i < b; i += 32) c += g_bsum[i];
        #pragma unroll
        for (int o = 16; o >= 1; o >>= 1) c += __shfl_xor_sync(0xffffffffu, c, o);
        if (t == 0) carry_s = c;
    }
    __syncthreads();
    if (b == 0 && t == 0) g_off[0] = 0;
    int i = b * 256 + t;
    if (i >= NN) return;
    int off = carry_s + g_off[i + 1];
    g_off[i + 1] = off;
    g_cur[i] = off - g_cnt[i];
}

__global__ void k_scatter(const void* __restrict__ ei) {
    int p = blockIdx.x * blockDim.x + threadIdx.x;
    if (p >= TE / 2) return;
    int s0, s1, d0, d1;
    if (2 * p < EE) {
        if (g_is64) {
            longlong2 sv = ((const longlong2*)ei)[p];
            longlong2 dv = ((const longlong2*)ei)[EE / 2 + p];
            s0 = (int)sv.x; s1 = (int)sv.y;
            d0 = (int)dv.x; d1 = (int)dv.y;
        } else {
            int2 sv = ((const int2*)ei)[p];
            int2 dv = ((const int2*)ei)[EE / 2 + p];
            s0 = sv.x; s1 = sv.y;
            d0 = dv.x; d1 = dv.y;
        }
    } else {
        s0 = d0 = 2 * p - EE;
        s1 = d1 = s0 + 1;
    }
    if (d0 == d1) {
        int pos = atomicAdd(&g_cur[d0], 2);
        g_csr[pos] = s0;
        g_csr[pos + 1] = s1;
    } else {
        g_csr[atomicAdd(&g_cur[d0], 1)] = s0;
        g_csr[atomicAdd(&g_cur[d1], 1)] = s1;
    }
}

// ---------------- fp16 mma -----------------------------------------------------
__device__ __forceinline__ void mma_f16(float c[4], const uint32_t a[4], const uint32_t b[2]) {
    asm("mma.sync.aligned.m16n8k16.row.col.f32.f16.f16.f32 "
        "{%0,%1,%2,%3},{%4,%5,%6,%7},{%8,%9},{%0,%1,%2,%3};"
        : "+f"(c[0]), "+f"(c[1]), "+f"(c[2]), "+f"(c[3])
        : "r"(a[0]), "r"(a[1]), "r"(a[2]), "r"(a[3]), "r"(b[0]), "r"(b[1]));
}

// ---------------- GEMM1: h1 = fp16(x) @ fp16(W1), fused att epilogue ---------
// (R12 baseline: scalar fragment loads, single-buffer smem)
#define SAH 40
#define SBH 40
__global__ void __launch_bounds__(256, 3)
k_gemm1(const float* __restrict__ att_s, const float* __restrict__ att_d) {
    __shared__ __align__(16) __half sAh[128 * SAH];   // 10.0 KB
    __shared__ __align__(16) __half sBh[64 * SBH];    // 5.0 KB
    __shared__ float parts[128][2];
    __shared__ float partd[128][2];

    int tid = threadIdx.x;
    int warp = tid >> 5, lane = tid & 31;
    int wm = (warp >> 1) * 32;
    int wnidx = warp & 1;
    int wn = wnidx * 32;
    int row0 = blockIdx.x * 128;
    int head = blockIdx.y;
    int col0 = head * 64;

    float acc[2][4][4];
    #pragma unroll
    for (int i = 0; i < 2; i++)
        #pragma unroll
        for (int j = 0; j < 4; j++)
            #pragma unroll
            for (int q = 0; q < 4; q++) acc[i][j][q] = 0.f;

    int ar = lane >> 2, ac = lane & 3;

    for (int chunk = 0; chunk < 4; chunk++) {
        int kk = chunk * 32;
        #pragma unroll
        for (int r = 0; r < 2; r++) {
            int idx = tid + 256 * r;
            int m = idx >> 2, q = idx & 3;
            int grow = row0 + m;
            uint4 vh = make_uint4(0u, 0u, 0u, 0u);
            if (grow < NN)
                vh = *(const uint4*)&g_xhp[(size_t)grow * FIN + kk + q * 8];
            *(uint4*)&sAh[m * SAH + q * 8] = vh;
        }
        {
            int n = tid >> 2, q = tid & 3;
            size_t g = (size_t)(col0 + n) * FIN + kk + q * 8;
            *(uint4*)&sBh[n * SBH + q * 8] = *(const uint4*)&g_wth[g];
        }
        __syncthreads();

        #pragma unroll
        for (int ks = 0; ks < 2; ks++) {
            int kb = ks * 16;
            uint32_t ah[2][4];
            #pragma unroll
            for (int mf = 0; mf < 2; mf++) {
                int mb = wm + mf * 16;
                int i0 = (mb + ar) * SAH + kb + 2 * ac;
                int i1 = (mb + ar + 8) * SAH + kb + 2 * ac;
                ah[mf][0] = *(const uint32_t*)&sAh[i0];
                ah[mf][1] = *(const uint32_t*)&sAh[i1];
                ah[mf][2] = *(const uint32_t*)&sAh[i0 + 8];
                ah[mf][3] = *(const uint32_t*)&sAh[i1 + 8];
            }
            uint32_t bh[4][2];
            #pragma unroll
            for (int nf = 0; nf < 4; nf++) {
                int col = wn + nf * 8 + (lane >> 2);
                int i0 = col * SBH + kb + 2 * (lane & 3);
                bh[nf][0] = *(const uint32_t*)&sBh[i0];
                bh[nf][1] = *(const uint32_t*)&sBh[i0 + 8];
            }
            #pragma unroll
            for (int mf = 0; mf < 2; mf++)
                #pragma unroll
                for (int nf = 0; nf < 4; nf++)
                    mma_f16(acc[mf][nf], ah[mf], bh[nf]);
        }
        __syncthreads();
    }

    float asv[4][2], adv[4][2];
    #pragma unroll
    for (int nf = 0; nf < 4; nf++) {
        int cb = head * HID + wn + nf * 8 + 2 * (lane & 3);
        asv[nf][0] = att_s[cb];     asv[nf][1] = att_s[cb + 1];
        adv[nf][0] = att_d[cb];     adv[nf][1] = att_d[cb + 1];
    }

    #pragma unroll
    for (int mf = 0; mf < 2; mf++) {
        int rA = row0 + wm + mf * 16 + (lane >> 2);
        int rB = rA + 8;
        float ps0 = 0.f, pd0 = 0.f, ps1 = 0.f, pd1 = 0.f;
        #pragma unroll
        for (int nf = 0; nf < 4; nf++) {
            int cb = col0 + wn + nf * 8 + 2 * (lane & 3);
            if (rA < NN)
                *(__half2*)&g_h1[(size_t)rA * C1 + cb] =
                    __floats2half2_rn(acc[mf][nf][0], acc[mf][nf][1]);
            if (rB < NN)
                *(__half2*)&g_h1[(size_t)rB * C1 + cb] =
                    __floats2half2_rn(acc[mf][nf][2], acc[mf][nf][3]);
            ps0 += acc[mf][nf][0] * asv[nf][0] + acc[mf][nf][1] * asv[nf][1];
            pd0 += acc[mf][nf][0] * adv[nf][0] + acc[mf][nf][1] * adv[nf][1];
            ps1 += acc[mf][nf][2] * asv[nf][0] + acc[mf][nf][3] * asv[nf][1];
            pd1 += acc[mf][nf][2] * adv[nf][0] + acc[mf][nf][3] * adv[nf][1];
        }
        #pragma unroll
        for (int o = 1; o <= 2; o <<= 1) {
            ps0 += __shfl_xor_sync(0xffffffffu, ps0, o);
            pd0 += __shfl_xor_sync(0xffffffffu, pd0, o);
            ps1 += __shfl_xor_sync(0xffffffffu, ps1, o);
            pd1 += __shfl_xor_sync(0xffffffffu, pd1, o);
        }
        if ((lane & 3) == 0) {
            int lr0 = wm + mf * 16 + (lane >> 2);
            parts[lr0][wnidx] = ps0;
            partd[lr0][wnidx] = pd0;
            parts[lr0 + 8][wnidx] = ps1;
            partd[lr0 + 8][wnidx] = pd1;
        }
    }
    __syncthreads();
    if (tid < 128) {
        int grow = row0 + tid;
        if (grow < NN) {
            g_as1[grow * HEADS + head] = parts[tid][0] + parts[tid][1];
            g_ad1[grow * HEADS + head] = partd[tid][0] + partd[tid][1];
        }
    }
}

// ---------------- layer-1 aggregation: 4 warps/node, 8-edge groups ----------
// Warp covers quarter qh (128 channels = heads 2qh, 2qh+1). Lane owns 4
// channels (one uint2 of fp16). Lanes 0-15 compute logits: lane = 2*edge + headbit.
__global__ void k_agg1(const float* __restrict__ b1, const float* __restrict__ W2,
                       const float* __restrict__ att_s2, const float* __restrict__ att_d2) {
    __shared__ float sW2[C1 * 2];
    __shared__ float sb1[C1];
    __shared__ float pp[2][4][2];   // [node-in-block][quarter][p0/p1]
    int tid = threadIdx.x;
    for (int j = tid; j < C1 * 2; j += 256) sW2[j] = W2[j];
    for (int j = tid; j < C1; j += 256) sb1[j] = b1[j];
    __syncthreads();

    int warp = tid >> 5, lane = tid & 31;
    int nidx = warp >> 2, qh = warp & 3;          // 2 nodes/block, 4 warps/node
    int node = blockIdx.x * 2 + nidx;             // NN % 2 == 0 -> always valid
    int hb_own = lane >> 4;                       // owned-channel head bit (0/1)
    int jj = lane >> 1, hb = lane & 1;            // logit assignment (lanes 0-15)

    int beg = g_off[node], end = g_off[node + 1];
    float adst_r = (lane < 2) ? g_ad1[node * HEADS + 2 * qh + lane] : 0.f;
    float adh = __shfl_sync(0xffffffffu, adst_r, hb);   // adst for head 2qh+hb

    float s = 0.f;
    float acc[4] = {0.f, 0.f, 0.f, 0.f};

    const __half* hbase = g_h1 + qh * 128 + lane * 4;

    for (int e = beg; e < end; e += 8) {
        int m = end - e; if (m > 8) m = 8;
        float w = 0.f;
        int sj = 0;
        if (lane < 16 && jj < m) {
            sj = g_csr[e + jj];
            float a = g_as1[sj * HEADS + 2 * qh + hb] + adh;
            a = a > 0.f ? a : 0.2f * a;
            w = __expf(a);
            s += w;
        }
        #pragma unroll
        for (int q = 0; q < 8; q++) {
            if (q < m) {
                int srcq = __shfl_sync(0xffffffffu, sj, 2 * q);
                float wq = __shfl_sync(0xffffffffu, w, 2 * q + hb_own);
                uint2 u = *(const uint2*)(hbase + (size_t)srcq * C1);
                float2 f0 = __half22float2(*(const __half2*)&u.x);
                float2 f1 = __half22float2(*(const __half2*)&u.y);
                acc[0] += wq * f0.x; acc[1] += wq * f0.y;
                acc[2] += wq * f1.x; acc[3] += wq * f1.y;
            }
        }
    }

    // per-head softmax sums: sum over edge bits (1,2,3) preserving head bit 0
    s += __shfl_xor_sync(0xffffffffu, s, 2);
    s += __shfl_xor_sync(0xffffffffu, s, 4);
    s += __shfl_xor_sync(0xffffffffu, s, 8);
    float inv = 1.f / __shfl_sync(0xffffffffu, s, hb_own);   // lane 0 or 1

    // partial layer-2 dot over this quarter's 128 channels
    float p0 = 0.f, p1 = 0.f;
    #pragma unroll
    for (int j = 0; j < 4; j++) {
        int ch = qh * 128 + lane * 4 + j;
        float o = acc[j] * inv + sb1[ch];
        float he = o > 0.f ? o : expm1f(o);
        p0 += he * sW2[ch * 2 + 0];
        p1 += he * sW2[ch * 2 + 1];
    }
    #pragma unroll
    for (int off = 16; off >= 1; off >>= 1) {
        p0 += __shfl_xor_sync(0xffffffffu, p0, off);
        p1 += __shfl_xor_sync(0xffffffffu, p1, off);
    }
    if (lane == 0) {
        pp[nidx][qh][0] = p0;
        pp[nidx][qh][1] = p1;
    }
    __syncthreads();
    if (qh == 0 && lane == 0) {
        float q0 = pp[nidx][0][0] + pp[nidx][1][0] + pp[nidx][2][0] + pp[nidx][3][0];
        float q1 = pp[nidx][0][1] + pp[nidx][1][1] + pp[nidx][2][1] + pp[nidx][3][1];
        g_h2[node * 2 + 0] = q0;
        g_h2[node * 2 + 1] = q1;
        g_as2[node] = q0 * att_s2[0] + q1 * att_s2[1];
        g_ad2[node] = q0 * att_d2[0] + q1 * att_d2[1];
    }
}

// ---------------- layer-2 aggregation (+ g_cnt re-zero for next call) --------
__global__ void k_agg2(const float* __restrict__ b2, float* __restrict__ out) {
    int tid = threadIdx.x;
    int gi = blockIdx.x * 256 + tid;
    if (gi < NN) g_cnt[gi] = 0;
    int node = gi >> 5;
    if (node >= NN) return;
    int lane = tid & 31;

    int beg = g_off[node], end = g_off[node + 1];
    float adst = g_ad2[node];

    float s = 0.f, a0 = 0.f, a1 = 0.f;
    for (int e = beg + lane; e < end; e += 32) {
        int src = g_csr[e];
        float al = g_as2[src] + adst;
        al = al > 0.f ? al : 0.2f * al;
        float w = __expf(al);
        s  += w;
        a0 += w * g_h2[src * 2 + 0];
        a1 += w * g_h2[src * 2 + 1];
    }
    #pragma unroll
    for (int off = 16; off >= 1; off >>= 1) {
        s  += __shfl_xor_sync(0xffffffffu, s,  off);
        a0 += __shfl_xor_sync(0xffffffffu, a0, off);
        a1 += __shfl_xor_sync(0xffffffffu, a1, off);
    }
    if (lane == 0) {
        float inv = 1.f / s;
        out[node * 2 + 0] = a0 * inv + b2[0];
        out[node * 2 + 1] = a1 * inv + b2[1];
    }
}

// ---------------- launch: two-stream overlap inside graph capture -------------
static cudaStream_t g_s2 = nullptr;
static cudaEvent_t  g_evf = nullptr, g_evj = nullptr;

extern "C" void kernel_launch(void* const* d_in, const int* in_sizes, int n_in,
                              void* d_out, int out_size) {
    const float* x   = (const float*)d_in[0];
    const void*  ei  = d_in[1];
    const float* W1  = (const float*)d_in[2];
    const float* as1 = (const float*)d_in[3];
    const float* ad1 = (const float*)d_in[4];
    const float* b1  = (const float*)d_in[5];
    const float* W2  = (const float*)d_in[6];
    const float* as2 = (const float*)d_in[7];
    const float* ad2 = (const float*)d_in[8];
    const float* b2  = (const float*)d_in[9];
    float* out = (float*)d_out;

    if (g_s2 == nullptr) {   // first call is the uncaptured correctness run
        cudaStreamCreateWithFlags(&g_s2, cudaStreamNonBlocking);
        cudaEventCreateWithFlags(&g_evf, cudaEventDisableTiming);
        cudaEventCreateWithFlags(&g_evj, cudaEventDisableTiming);
    }

    // fork: side stream builds CSR while main stream converts + runs GEMM1
    cudaEventRecord(g_evf, 0);
    cudaStreamWaitEvent(g_s2, g_evf, 0);

    k_count<<<CB, 256, 0, g_s2>>>(ei);
    k_scanA<<<NBLK, 256, 0, g_s2>>>();
    k_scanC<<<NBLK, 256, 0, g_s2>>>();
    k_scatter<<<CB, 256, 0, g_s2>>>(ei);
    cudaEventRecord(g_evj, g_s2);

    k_conv<<<XB + WB, 256>>>(x, W1);
    k_gemm1<<<dim3((NN + 127) / 128, HEADS), 256>>>(as1, ad1);

    // join: aggregation needs both CSR and h1
    cudaStreamWaitEvent(0, g_evj, 0);
    k_agg1<<<NN / 2, 256>>>(b1, W2, as2, ad2);
    k_agg2<<<(NN * 32 + 255) / 256, 256>>>(b2, out);
}

// round 16
// speedup vs baseline: 1.2287x; 1.2287x over previous
#include <cuda_runtime.h>
#include <cuda_fp16.h>
#include <cstdint>

#define NN 20000
#define EE 320000
#define TE (EE + NN)          // edges + self loops
#define FIN 128
#define HID 64
#define HEADS 8
#define C1 (HEADS * HID)      // 512
#define NBLK ((NN + 255) / 256)   // 79 scan blocks
#define CB ((TE / 2 + 255) / 256) // 665 count/scatter blocks
#define XB (NN * FIN / 4 / 256)   // 2500 x-convert blocks
#define WB (FIN * C1 / 256)       // 256 w-convert blocks

// ---------------- scratch (static device globals; no allocation) -------------
__device__ int    g_is64;
__device__ int    g_cnt[NN];
__device__ int    g_off[NN + 1];
__device__ int    g_cur[NN];
__device__ int    g_csr[TE];
__device__ int    g_bsum[NBLK];
__device__ __half g_h1[(size_t)NN * C1];      // 20 MB, fp16 features
__device__ __half g_xhp[(size_t)NN * FIN];    // fp16 x            [N][128]
__device__ __half g_wth[C1 * FIN];            // fp16 W1^T         [n][k]
__device__ float  g_as1[NN * HEADS];
__device__ float  g_ad1[NN * HEADS];
__device__ float  g_h2[NN * 2];
__device__ float  g_as2[NN];
__device__ float  g_ad2[NN];

// ---------------- conversions: x->fp16 + W1^T->fp16 (main stream) ------------
__global__ void k_conv(const float* __restrict__ x, const float* __restrict__ W1) {
    int b = blockIdx.x, t = threadIdx.x;
    if (b < XB) {
        int i = b * 256 + t;
        float4 v = ((const float4*)x)[i];
        ((__half2*)g_xhp)[2 * i + 0] = __floats2half2_rn(v.x, v.y);
        ((__half2*)g_xhp)[2 * i + 1] = __floats2half2_rn(v.z, v.w);
    } else {
        int j = (b - XB) * 256 + t;
        int k = j / C1, n = j % C1;
        g_wth[n * FIN + k] = __float2half_rn(W1[j]);
    }
}

// ---------------- CSR build (side stream) -------------------------------------
__global__ void k_count(const void* __restrict__ ei) {
    __shared__ int is64_s;
    int b = blockIdx.x, t = threadIdx.x;
    if (t < 32) {
        int hi = ((const int*)ei)[2 * t + 1];
        unsigned bl = __ballot_sync(0xffffffffu, hi == 0);
        if (t == 0) {
            is64_s = (bl == 0xffffffffu) ? 1 : 0;
            if (b == 0) g_is64 = is64_s;
        }
    }
    __syncthreads();
    int p = b * 256 + t;
    if (p >= TE / 2) return;
    int d0, d1;
    if (2 * p < EE) {
        if (is64_s) {
            longlong2 v = ((const longlong2*)ei)[EE / 2 + p];
            d0 = (int)v.x; d1 = (int)v.y;
        } else {
            int2 v = ((const int2*)ei)[EE / 2 + p];
            d0 = v.x; d1 = v.y;
        }
    } else {
        d0 = 2 * p - EE; d1 = d0 + 1;
    }
    if (d0 == d1) atomicAdd(&g_cnt[d0], 2);
    else { atomicAdd(&g_cnt[d0], 1); atomicAdd(&g_cnt[d1], 1); }
}

__global__ void k_scanA() {
    int t = threadIdx.x, b = blockIdx.x;
    int i = b * 256 + t;
    int v = (i < NN) ? g_cnt[i] : 0;
    int lane = t & 31, wid = t >> 5;
    int incl = v;
    #pragma unroll
    for (int o = 1; o < 32; o <<= 1) {
        int x = __shfl_up_sync(0xffffffffu, incl, o);
        if (lane >= o) incl += x;
    }
    __shared__ int ws[8];
    if (lane == 31) ws[wid] = incl;
    __syncthreads();
    if (t < 8) {
        int wv = ws[t];
        int wincl = wv;
        #pragma unroll
        for (int o = 1; o < 8; o <<= 1) {
            int x = __shfl_up_sync(0x000000ffu, wincl, o);
            if (t >= o) wincl += x;
        }
        ws[t] = wincl - wv;
        if (t == 7) g_bsum[b] = wincl;
    }
    __syncthreads();
    incl += ws[wid];
    if (i < NN) g_off[i + 1] = incl;
}

__global__ void k_scanC() {
    __shared__ int carry_s;
    int t = threadIdx.x, b = blockIdx.x;
    if (t < 32) {
        int c = 0;
        for (int i = t; i < b; i += 32) c += g_bsum[i];
        #pragma unroll
        for (int o = 16; o >= 1; o >>= 1) c += __shfl_xor_sync(0xffffffffu, c, o);
        if (t == 0) carry_s = c;
    }
    __syncthreads();
    if (b == 0 && t == 0) g_off[0] = 0;
    int i = b * 256 + t;
    if (i >= NN) return;
    int off = carry_s + g_off[i + 1];
    g_off[i + 1] = off;
    g_cur[i] = off - g_cnt[i];
}

__global__ void k_scatter(const void* __restrict__ ei) {
    int p = blockIdx.x * blockDim.x + threadIdx.x;
    if (p >= TE / 2) return;
    int s0, s1, d0, d1;
    if (2 * p < EE) {
        if (g_is64) {
            longlong2 sv = ((const longlong2*)ei)[p];
            longlong2 dv = ((const longlong2*)ei)[EE / 2 + p];
            s0 = (int)sv.x; s1 = (int)sv.y;
            d0 = (int)dv.x; d1 = (int)dv.y;
        } else {
            int2 sv = ((const int2*)ei)[p];
            int2 dv = ((const int2*)ei)[EE / 2 + p];
            s0 = sv.x; s1 = sv.y;
            d0 = dv.x; d1 = dv.y;
        }
    } else {
        s0 = d0 = 2 * p - EE;
        s1 = d1 = s0 + 1;
    }
    if (d0 == d1) {
        int pos = atomicAdd(&g_cur[d0], 2);
        g_csr[pos] = s0;
        g_csr[pos + 1] = s1;
    } else {
        g_csr[atomicAdd(&g_cur[d0], 1)] = s0;
        g_csr[atomicAdd(&g_cur[d1], 1)] = s1;
    }
}

// ---------------- fp16 mma -----------------------------------------------------
__device__ __forceinline__ void mma_f16(float c[4], const uint32_t a[4], const uint32_t b[2]) {
    asm("mma.sync.aligned.m16n8k16.row.col.f32.f16.f16.f32 "
        "{%0,%1,%2,%3},{%4,%5,%6,%7},{%8,%9},{%0,%1,%2,%3};"
        : "+f"(c[0]), "+f"(c[1]), "+f"(c[2]), "+f"(c[3])
        : "r"(a[0]), "r"(a[1]), "r"(a[2]), "r"(a[3]), "r"(b[0]), "r"(b[1]));
}

// ---------------- GEMM1: h1 = fp16(x) @ fp16(W1), fused att epilogue ---------
// grid (157, 8) ; block 256 = 8 warps (4 m x 2 n); BM=128 BN=64 BK=32
// R15 change: launch_bounds occupancy 3 -> 4 (regs capped at 64)
#define SAH 40
#define SBH 40
__global__ void __launch_bounds__(256, 4)
k_gemm1(const float* __restrict__ att_s, const float* __restrict__ att_d) {
    __shared__ __align__(16) __half sAh[128 * SAH];   // 10.0 KB
    __shared__ __align__(16) __half sBh[64 * SBH];    // 5.0 KB
    __shared__ float parts[128][2];
    __shared__ float partd[128][2];

    int tid = threadIdx.x;
    int warp = tid >> 5, lane = tid & 31;
    int wm = (warp >> 1) * 32;
    int wnidx = warp & 1;
    int wn = wnidx * 32;
    int row0 = blockIdx.x * 128;
    int head = blockIdx.y;
    int col0 = head * 64;

    float acc[2][4][4];
    #pragma unroll
    for (int i = 0; i < 2; i++)
        #pragma unroll
        for (int j = 0; j < 4; j++)
            #pragma unroll
            for (int q = 0; q < 4; q++) acc[i][j][q] = 0.f;

    int ar = lane >> 2, ac = lane & 3;

    for (int chunk = 0; chunk < 4; chunk++) {
        int kk = chunk * 32;
        #pragma unroll
        for (int r = 0; r < 2; r++) {
            int idx = tid + 256 * r;
            int m = idx >> 2, q = idx & 3;
            int grow = row0 + m;
            uint4 vh = make_uint4(0u, 0u, 0u, 0u);
            if (grow < NN)
                vh = *(const uint4*)&g_xhp[(size_t)grow * FIN + kk + q * 8];
            *(uint4*)&sAh[m * SAH + q * 8] = vh;
        }
        {
            int n = tid >> 2, q = tid & 3;
            size_t g = (size_t)(col0 + n) * FIN + kk + q * 8;
            *(uint4*)&sBh[n * SBH + q * 8] = *(const uint4*)&g_wth[g];
        }
        __syncthreads();

        #pragma unroll
        for (int ks = 0; ks < 2; ks++) {
            int kb = ks * 16;
            uint32_t ah[2][4];
            #pragma unroll
            for (int mf = 0; mf < 2; mf++) {
                int mb = wm + mf * 16;
                int i0 = (mb + ar) * SAH + kb + 2 * ac;
                int i1 = (mb + ar + 8) * SAH + kb + 2 * ac;
                ah[mf][0] = *(const uint32_t*)&sAh[i0];
                ah[mf][1] = *(const uint32_t*)&sAh[i1];
                ah[mf][2] = *(const uint32_t*)&sAh[i0 + 8];
                ah[mf][3] = *(const uint32_t*)&sAh[i1 + 8];
            }
            uint32_t bh[4][2];
            #pragma unroll
            for (int nf = 0; nf < 4; nf++) {
                int col = wn + nf * 8 + (lane >> 2);
                int i0 = col * SBH + kb + 2 * (lane & 3);
                bh[nf][0] = *(const uint32_t*)&sBh[i0];
                bh[nf][1] = *(const uint32_t*)&sBh[i0 + 8];
            }
            #pragma unroll
            for (int mf = 0; mf < 2; mf++)
                #pragma unroll
                for (int nf = 0; nf < 4; nf++)
                    mma_f16(acc[mf][nf], ah[mf], bh[nf]);
        }
        __syncthreads();
    }

    // ---- epilogue: store h1 (fp16) + fused attention dots ------------------
    float asv[4][2], adv[4][2];
    #pragma unroll
    for (int nf = 0; nf < 4; nf++) {
        int cb = head * HID + wn + nf * 8 + 2 * (lane & 3);
        asv[nf][0] = att_s[cb];     asv[nf][1] = att_s[cb + 1];
        adv[nf][0] = att_d[cb];     adv[nf][1] = att_d[cb + 1];
    }

    #pragma unroll
    for (int mf = 0; mf < 2; mf++) {
        int rA = row0 + wm + mf * 16 + (lane >> 2);
        int rB = rA + 8;
        float ps0 = 0.f, pd0 = 0.f, ps1 = 0.f, pd1 = 0.f;
        #pragma unroll
        for (int nf = 0; nf < 4; nf++) {
            int cb = col0 + wn + nf * 8 + 2 * (lane & 3);
            if (rA < NN)
                *(__half2*)&g_h1[(size_t)rA * C1 + cb] =
                    __floats2half2_rn(acc[mf][nf][0], acc[mf][nf][1]);
            if (rB < NN)
                *(__half2*)&g_h1[(size_t)rB * C1 + cb] =
                    __floats2half2_rn(acc[mf][nf][2], acc[mf][nf][3]);
            ps0 += acc[mf][nf][0] * asv[nf][0] + acc[mf][nf][1] * asv[nf][1];
            pd0 += acc[mf][nf][0] * adv[nf][0] + acc[mf][nf][1] * adv[nf][1];
            ps1 += acc[mf][nf][2] * asv[nf][0] + acc[mf][nf][3] * asv[nf][1];
            pd1 += acc[mf][nf][2] * adv[nf][0] + acc[mf][nf][3] * adv[nf][1];
        }
        #pragma unroll
        for (int o = 1; o <= 2; o <<= 1) {
            ps0 += __shfl_xor_sync(0xffffffffu, ps0, o);
            pd0 += __shfl_xor_sync(0xffffffffu, pd0, o);
            ps1 += __shfl_xor_sync(0xffffffffu, ps1, o);
            pd1 += __shfl_xor_sync(0xffffffffu, pd1, o);
        }
        if ((lane & 3) == 0) {
            int lr0 = wm + mf * 16 + (lane >> 2);
            parts[lr0][wnidx] = ps0;
            partd[lr0][wnidx] = pd0;
            parts[lr0 + 8][wnidx] = ps1;
            partd[lr0 + 8][wnidx] = pd1;
        }
    }
    __syncthreads();
    if (tid < 128) {
        int grow = row0 + tid;
        if (grow < NN) {
            g_as1[grow * HEADS + head] = parts[tid][0] + parts[tid][1];
            g_ad1[grow * HEADS + head] = partd[tid][0] + partd[tid][1];
        }
    }
}

// ---------------- layer-1 aggregation: 2 warps/node, 8-edge groups (R12) -----
__device__ __forceinline__ void acc_u4(float* acc, const uint4& u, float w) {
    float2 f0 = __half22float2(*(const __half2*)&u.x);
    float2 f1 = __half22float2(*(const __half2*)&u.y);
    float2 f2 = __half22float2(*(const __half2*)&u.z);
    float2 f3 = __half22float2(*(const __half2*)&u.w);
    acc[0] += w * f0.x; acc[1] += w * f0.y;
    acc[2] += w * f1.x; acc[3] += w * f1.y;
    acc[4] += w * f2.x; acc[5] += w * f2.y;
    acc[6] += w * f3.x; acc[7] += w * f3.y;
}

__global__ void k_agg1(const float* __restrict__ b1, const float* __restrict__ W2,
                       const float* __restrict__ att_s2, const float* __restrict__ att_d2) {
    __shared__ float sW2[C1 * 2];
    __shared__ float sb1[C1];
    __shared__ float pp[4][2][2];
    int tid = threadIdx.x;
    for (int j = tid; j < C1 * 2; j += 256) sW2[j] = W2[j];
    for (int j = tid; j < C1; j += 256) sb1[j] = b1[j];
    __syncthreads();

    int warp = tid >> 5, lane = tid & 31;
    int nidx = warp >> 1, wh = warp & 1;
    int node = blockIdx.x * 4 + nidx;
    int hh = lane >> 3;
    int jj = lane >> 2, h4 = lane & 3;

    int beg = g_off[node], end = g_off[node + 1];
    float adst_r = (lane < 4) ? g_ad1[node * HEADS + wh * 4 + lane] : 0.f;
    float adh = __shfl_sync(0xffffffffu, adst_r, h4);

    float s = 0.f;
    float acc[8];
    #pragma unroll
    for (int j = 0; j < 8; j++) acc[j] = 0.f;

    const __half* hbase = g_h1 + wh * 256 + lane * 8;

    for (int e = beg; e < end; e += 8) {
        int m = end - e; if (m > 8) m = 8;
        float w = 0.f;
        if (jj < m) {
            int sj = g_csr[e + jj];
            float a = g_as1[sj * HEADS + wh * 4 + h4] + adh;
            a = a > 0.f ? a : 0.2f * a;
            w = __expf(a);
            s += w;
        }
        #pragma unroll
        for (int q = 0; q < 8; q++) {
            if (q < m) {
                int srcq = g_csr[e + q];
                float wq = __shfl_sync(0xffffffffu, w, 4 * q + hh);
                uint4 u = *(const uint4*)(hbase + (size_t)srcq * C1);
                acc_u4(acc, u, wq);
            }
        }
    }

    s += __shfl_xor_sync(0xffffffffu, s, 4);
    s += __shfl_xor_sync(0xffffffffu, s, 8);
    s += __shfl_xor_sync(0xffffffffu, s, 16);
    float inv = 1.f / __shfl_sync(0xffffffffu, s, hh);

    float p0 = 0.f, p1 = 0.f;
    #pragma unroll
    for (int j = 0; j < 8; j++) {
        int ch = wh * 256 + lane * 8 + j;
        float o = acc[j] * inv + sb1[ch];
        float he = o > 0.f ? o : expm1f(o);
        p0 += he * sW2[ch * 2 + 0];
        p1 += he * sW2[ch * 2 + 1];
    }
    #pragma unroll
    for (int off = 16; off >= 1; off >>= 1) {
        p0 += __shfl_xor_sync(0xffffffffu, p0, off);
        p1 += __shfl_xor_sync(0xffffffffu, p1, off);
    }
    if (lane == 0) {
        pp[nidx][wh][0] = p0;
        pp[nidx][wh][1] = p1;
    }
    __syncthreads();
    if (wh == 0 && lane == 0) {
        float q0 = pp[nidx][0][0] + pp[nidx][1][0];
        float q1 = pp[nidx][0][1] + pp[nidx][1][1];
        g_h2[node * 2 + 0] = q0;
        g_h2[node * 2 + 1] = q1;
        g_as2[node] = q0 * att_s2[0] + q1 * att_s2[1];
        g_ad2[node] = q0 * att_d2[0] + q1 * att_d2[1];
    }
}

// ---------------- layer-2 aggregation (+ g_cnt re-zero for next call) --------
__global__ void k_agg2(const float* __restrict__ b2, float* __restrict__ out) {
    int tid = threadIdx.x;
    int gi = blockIdx.x * 256 + tid;
    if (gi < NN) g_cnt[gi] = 0;
    int node = gi >> 5;
    if (node >= NN) return;
    int lane = tid & 31;

    int beg = g_off[node], end = g_off[node + 1];
    float adst = g_ad2[node];

    float s = 0.f, a0 = 0.f, a1 = 0.f;
    for (int e = beg + lane; e < end; e += 32) {
        int src = g_csr[e];
        float al = g_as2[src] + adst;
        al = al > 0.f ? al : 0.2f * al;
        float w = __expf(al);
        s  += w;
        a0 += w * g_h2[src * 2 + 0];
        a1 += w * g_h2[src * 2 + 1];
    }
    #pragma unroll
    for (int off = 16; off >= 1; off >>= 1) {
        s  += __shfl_xor_sync(0xffffffffu, s,  off);
        a0 += __shfl_xor_sync(0xffffffffu, a0, off);
        a1 += __shfl_xor_sync(0xffffffffu, a1, off);
    }
    if (lane == 0) {
        float inv = 1.f / s;
        out[node * 2 + 0] = a0 * inv + b2[0];
        out[node * 2 + 1] = a1 * inv + b2[1];
    }
}

// ---------------- launch: two-stream overlap inside graph capture -------------
static cudaStream_t g_s2 = nullptr;
static cudaEvent_t  g_evf = nullptr, g_evj = nullptr;

extern "C" void kernel_launch(void* const* d_in, const int* in_sizes, int n_in,
                              void* d_out, int out_size) {
    const float* x   = (const float*)d_in[0];
    const void*  ei  = d_in[1];
    const float* W1  = (const float*)d_in[2];
    const float* as1 = (const float*)d_in[3];
    const float* ad1 = (const float*)d_in[4];
    const float* b1  = (const float*)d_in[5];
    const float* W2  = (const float*)d_in[6];
    const float* as2 = (const float*)d_in[7];
    const float* ad2 = (const float*)d_in[8];
    const float* b2  = (const float*)d_in[9];
    float* out = (float*)d_out;

    if (g_s2 == nullptr) {   // first call is the uncaptured correctness run
        cudaStreamCreateWithFlags(&g_s2, cudaStreamNonBlocking);
        cudaEventCreateWithFlags(&g_evf, cudaEventDisableTiming);
        cudaEventCreateWithFlags(&g_evj, cudaEventDisableTiming);
    }

    // fork: side stream builds CSR while main stream converts + runs GEMM1
    cudaEventRecord(g_evf, 0);
    cudaStreamWaitEvent(g_s2, g_evf, 0);

    k_count<<<CB, 256, 0, g_s2>>>(ei);
    k_scanA<<<NBLK, 256, 0, g_s2>>>();
    k_scanC<<<NBLK, 256, 0, g_s2>>>();
    k_scatter<<<CB, 256, 0, g_s2>>>(ei);
    cudaEventRecord(g_evj, g_s2);

    k_conv<<<XB + WB, 256>>>(x, W1);
    k_gemm1<<<dim3((NN + 127) / 128, HEADS), 256>>>(as1, ad1);

    // join: aggregation needs both CSR and h1
    cudaStreamWaitEvent(0, g_evj, 0);
    k_agg1<<<NN / 4, 256>>>(b1, W2, as2, ad2);
    k_agg2<<<(NN * 32 + 255) / 256, 256>>>(b2, out);
}